// round 11
// baseline (speedup 1.0000x reference)
#include <cuda_runtime.h>
#include <cuda_bf16.h>

// CSR multi-head SpMM: out[n,h,d] = sum_{e in row n} ew[e,h] * nf[col[e],h,d]
// N=50000, E=800000, H=8, D=8 -> 64 floats per row.
//
// R10: nnz-balanced edge tiles (R9, validated: occ 83%, issue 47%) with a
// slimmer inner loop:
//  - segment-boundary bitmask built once per tile via shfl_down + ballot;
//    inner loop tests a uniform register bit (no per-iter LDS/compare).
//  - dst row id at flush via __shfl_sync (sdst smem removed).
//  - interior segments (start>0 AND end<31) are tile-private -> plain
//    STG.64 over the memset zeros; only first-segment / tile-end flushes
//    need atomicAdd.
//  - edge_weight streamed with __ldcs (no reuse; keep L2 for node_feat).

#define H 8
#define D 8
#define ROW_ELEMS (H * D)
#define TILE 32
#define WPB 4            // warps per block in spmm kernel
#define MAX_EDGES 800000
#define FULLMASK 0xffffffffu

__device__ int g_dst[MAX_EDGES];

__global__ __launch_bounds__(256) void fill_dst_kernel(
    const int* __restrict__ row_ptr, int n_nodes)
{
    int i = blockIdx.x * blockDim.x + threadIdx.x;
    if (i >= n_nodes) return;
    int s = __ldg(&row_ptr[i]);
    int e = __ldg(&row_ptr[i + 1]);
    for (int j = s; j < e; ++j) g_dst[j] = i;   // fire-and-forget stores
}

__global__ __launch_bounds__(32 * WPB) void spmm_balanced_kernel(
    const int* __restrict__ col_idx,
    const float* __restrict__ edge_weight,   // [E, 8]
    const float* __restrict__ node_feat,     // [N, 64]
    float* __restrict__ out,                 // [N, 64]
    int n_edges)
{
    __shared__ int scol[WPB][TILE];

    int wip  = threadIdx.x >> 5;
    int lane = threadIdx.x & 31;
    int tile = blockIdx.x * WPB + wip;
    int base = tile * TILE;
    if (base >= n_edges) return;

    // stage: this lane's edge index (clamped), column, destination row
    int e   = base + lane;
    int idx = (e < n_edges) ? e : (n_edges - 1);
    int my_col = __ldg(&col_idx[idx]);
    int my_dst = __ldg(&g_dst[idx]);
    scol[wip][lane] = my_col;
    __syncwarp();

    int h = lane >> 2;                 // head for this lane's float2
    float ax = 0.0f, ay = 0.0f;

    if (base + TILE <= n_edges) {
        // boundary mask: bit j set iff segment ends at edge j (uniform reg)
        int nxt = __shfl_down_sync(FULLMASK, my_dst, 1);
        bool bnd = (lane == 31) ? true : (my_dst != nxt);
        unsigned bmask = __ballot_sync(FULLMASK, bnd);

        bool firstseg = true;
        #pragma unroll 4
        for (int j = 0; j < TILE; ++j) {
            int c   = scol[wip][j];                       // LDS broadcast
            float w = __ldcs(&edge_weight[(size_t)(base + j) * H + h]);
            float2 f = *reinterpret_cast<const float2*>(
                node_feat + (size_t)c * ROW_ELEMS + lane * 2);
            ax = fmaf(w, f.x, ax);
            ay = fmaf(w, f.y, ay);

            if ((bmask >> j) & 1u) {                      // uniform branch
                int drow = __shfl_sync(FULLMASK, my_dst, j);
                float* o = out + (size_t)drow * ROW_ELEMS + lane * 2;
                if (firstseg || j == TILE - 1) {
                    // may span tile boundary -> atomic
                    atomicAdd(o,     ax);
                    atomicAdd(o + 1, ay);
                } else {
                    // interior segment: tile-private row -> plain store
                    float2 r; r.x = ax; r.y = ay;
                    *reinterpret_cast<float2*>(o) = r;
                }
                firstseg = false;
                ax = 0.0f; ay = 0.0f;
            }
        }
    } else {
        // tail tile (not hit when E % 32 == 0): always atomic
        int nb = n_edges - base;
        for (int j = 0; j < nb; ++j) {
            int c   = scol[wip][j];
            float w = __ldcs(&edge_weight[(size_t)(base + j) * H + h]);
            float2 f = *reinterpret_cast<const float2*>(
                node_feat + (size_t)c * ROW_ELEMS + lane * 2);
            ax = fmaf(w, f.x, ax);
            ay = fmaf(w, f.y, ay);
            int dj  = __shfl_sync(FULLMASK, my_dst, j);
            int dj1 = __shfl_sync(FULLMASK, my_dst, (j + 1 < nb) ? j + 1 : j);
            if (j == nb - 1 || dj != dj1) {
                float* o = out + (size_t)dj * ROW_ELEMS + lane * 2;
                atomicAdd(o,     ax);
                atomicAdd(o + 1, ay);
                ax = 0.0f; ay = 0.0f;
            }
        }
    }
}

extern "C" void kernel_launch(void* const* d_in, const int* in_sizes, int n_in,
                              void* d_out, int out_size)
{
    const int*   row_ptr     = (const int*)d_in[0];
    const int*   col_idx     = (const int*)d_in[1];
    const float* edge_weight = (const float*)d_in[2];
    const float* node_feat   = (const float*)d_in[3];
    float*       out         = (float*)d_out;

    int n_nodes = in_sizes[0] - 1;   // row_ptr has N+1 entries
    int n_edges = in_sizes[1];       // col_idx element count

    // k0: zero the output (atomic/STG accumulation target)
    cudaMemsetAsync(d_out, 0, (size_t)out_size * sizeof(float));

    // k1: per-edge destination rows
    int b1 = (n_nodes + 255) / 256;
    fill_dst_kernel<<<b1, 256>>>(row_ptr, n_nodes);

    // k2: balanced edge-tile SpMM
    int tiles = (n_edges + TILE - 1) / TILE;
    int b2 = (tiles + WPB - 1) / WPB;
    spmm_balanced_kernel<<<b2, 32 * WPB>>>(col_idx, edge_weight,
                                           node_feat, out, n_edges);
}

// round 12
// speedup vs baseline: 1.2714x; 1.2714x over previous
#include <cuda_runtime.h>
#include <cuda_bf16.h>

// CSR multi-head SpMM: out[n,h,d] = sum_{e in row n} ew[e,h] * nf[col[e],h,d]
// N=50000, E=800000, H=8, D=8 -> 64 floats per row.
//
// R11 = R9's validated balanced spmm (ncu 29.7us, occ 83%, issue 47%)
//       + warp-per-row fill_dst (was thread-per-row: 50k threads total,
//         occupancy-starved, ~170-iteration serial tail -> ~6us; now 50k
//         warps with coalesced 32-wide stores -> ~1.5us).
// R10's shfl/bitmask slimming REVERTED: per-iteration SHFL + data-dependent
// branch inside the unroll broke load batching (alu 16->24%, spmm +8us).

#define H 8
#define D 8
#define ROW_ELEMS (H * D)
#define TILE 32
#define WPB 4            // warps per block in spmm kernel
#define MAX_EDGES 800000

__device__ int g_dst[MAX_EDGES];

__global__ __launch_bounds__(256) void fill_dst_kernel(
    const int* __restrict__ row_ptr, int n_nodes)
{
    int warp = (blockIdx.x * blockDim.x + threadIdx.x) >> 5;
    int lane = threadIdx.x & 31;
    if (warp >= n_nodes) return;
    int s = __ldg(&row_ptr[warp]);
    int e = __ldg(&row_ptr[warp + 1]);
    for (int j = s + lane; j < e; j += 32)
        g_dst[j] = warp;                    // coalesced, fire-and-forget
}

__global__ __launch_bounds__(32 * WPB) void spmm_balanced_kernel(
    const int* __restrict__ col_idx,
    const float* __restrict__ edge_weight,   // [E, 8]
    const float* __restrict__ node_feat,     // [N, 64]
    float* __restrict__ out,                 // [N, 64]
    int n_edges)
{
    __shared__ int sdst[WPB][TILE];
    __shared__ int scol[WPB][TILE];

    int wip  = threadIdx.x >> 5;
    int lane = threadIdx.x & 31;
    int tile = blockIdx.x * WPB + wip;
    int base = tile * TILE;
    if (base >= n_edges) return;

    // stage this tile's 32 column indices + 32 destination rows (coalesced)
    int e   = base + lane;
    int idx = (e < n_edges) ? e : (n_edges - 1);
    scol[wip][lane] = __ldg(&col_idx[idx]);
    sdst[wip][lane] = __ldg(&g_dst[idx]);
    __syncwarp();

    int h = lane >> 2;
    float ax = 0.0f, ay = 0.0f;

    if (base + TILE <= n_edges) {
        // full tile: compile-time bound keeps load batching intact
        #pragma unroll 4
        for (int j = 0; j < TILE; ++j) {
            int c   = scol[wip][j];                       // LDS broadcast
            float w = __ldg(&edge_weight[(size_t)(base + j) * H + h]);
            float2 f = *reinterpret_cast<const float2*>(
                node_feat + (size_t)c * ROW_ELEMS + lane * 2);
            ax = fmaf(w, f.x, ax);
            ay = fmaf(w, f.y, ay);
            // warp-uniform flush at segment boundary / tile end
            if (j == TILE - 1 || sdst[wip][j + 1] != sdst[wip][j]) {
                float* o = out + (size_t)sdst[wip][j] * ROW_ELEMS + lane * 2;
                atomicAdd(o,     ax);
                atomicAdd(o + 1, ay);
                ax = 0.0f; ay = 0.0f;
            }
        }
    } else {
        int nb = n_edges - base;
        for (int j = 0; j < nb; ++j) {
            int c   = scol[wip][j];
            float w = __ldg(&edge_weight[(size_t)(base + j) * H + h]);
            float2 f = *reinterpret_cast<const float2*>(
                node_feat + (size_t)c * ROW_ELEMS + lane * 2);
            ax = fmaf(w, f.x, ax);
            ay = fmaf(w, f.y, ay);
            if (j == nb - 1 || sdst[wip][j + 1] != sdst[wip][j]) {
                float* o = out + (size_t)sdst[wip][j] * ROW_ELEMS + lane * 2;
                atomicAdd(o,     ax);
                atomicAdd(o + 1, ay);
                ax = 0.0f; ay = 0.0f;
            }
        }
    }
}

extern "C" void kernel_launch(void* const* d_in, const int* in_sizes, int n_in,
                              void* d_out, int out_size)
{
    const int*   row_ptr     = (const int*)d_in[0];
    const int*   col_idx     = (const int*)d_in[1];
    const float* edge_weight = (const float*)d_in[2];
    const float* node_feat   = (const float*)d_in[3];
    float*       out         = (float*)d_out;

    int n_nodes = in_sizes[0] - 1;   // row_ptr has N+1 entries
    int n_edges = in_sizes[1];       // col_idx element count

    // k0: zero the output (atomic accumulation target)
    cudaMemsetAsync(d_out, 0, (size_t)out_size * sizeof(float));

    // k1: per-edge destination rows (warp per row, coalesced)
    int b1 = (n_nodes * 32 + 255) / 256;
    fill_dst_kernel<<<b1, 256>>>(row_ptr, n_nodes);

    // k2: balanced edge-tile SpMM
    int tiles = (n_edges + TILE - 1) / TILE;
    int b2 = (tiles + WPB - 1) / WPB;
    spmm_balanced_kernel<<<b2, 32 * WPB>>>(col_idx, edge_weight,
                                           node_feat, out, n_edges);
}